// round 4
// baseline (speedup 1.0000x reference)
#include <cuda_runtime.h>
#include <math.h>

// Fixed problem shapes
#define Bb 16
#define Mm 1024
#define Ww 256
#define Hh 8
#define NWn 2
#define NRn 4

#define COPY_BLOCKS 4096
#define LINK_F4 ((size_t)Bb * NWn * Mm * Mm / 4)   // 8,388,608 float4

// ---------------------------------------------------------------------------
// One kernel. Blocks [0,16): per-batch fused compute (everything small).
// Blocks [16, 16+COPY_BLOCKS): grid-stride float4 copy of prev_link.
// ---------------------------------------------------------------------------
__global__ void __launch_bounds__(256) fused_kernel(
    const float* __restrict__ memory,
    const float* __restrict__ keys,
    const float* __restrict__ strengths,
    const float* __restrict__ ww,
    const float* __restrict__ fg,
    const float* __restrict__ rw,
    const float* __restrict__ prev_link,
    const float* __restrict__ pu,
    const float* __restrict__ ev,
    const float* __restrict__ wv,
    const float* __restrict__ rv,
    float* __restrict__ out_mem,
    float* __restrict__ out_cos,
    float* __restrict__ out_link,
    float* __restrict__ out_prec,
    float* __restrict__ out_usage,
    float* __restrict__ out_read)
{
    int tid = threadIdx.x;

    // ---------------- link copy blocks ----------------
    if (blockIdx.x >= 16) {
        const float4* __restrict__ src = (const float4*)prev_link;
        float4* __restrict__ dst = (float4*)out_link;
        size_t idx = (size_t)(blockIdx.x - 16) * 256 + tid;
        const size_t stride = (size_t)COPY_BLOCKS * 256;
        // 8 * stride == LINK_F4 exactly; 8 independent loads in flight
        float4 r0 = src[idx + 0 * stride];
        float4 r1 = src[idx + 1 * stride];
        float4 r2 = src[idx + 2 * stride];
        float4 r3 = src[idx + 3 * stride];
        float4 r4 = src[idx + 4 * stride];
        float4 r5 = src[idx + 5 * stride];
        float4 r6 = src[idx + 6 * stride];
        float4 r7 = src[idx + 7 * stride];
        dst[idx + 0 * stride] = r0;
        dst[idx + 1 * stride] = r1;
        dst[idx + 2 * stride] = r2;
        dst[idx + 3 * stride] = r3;
        dst[idx + 4 * stride] = r4;
        dst[idx + 5 * stride] = r5;
        dst[idx + 6 * stride] = r6;
        dst[idx + 7 * stride] = r7;
        return;
    }

    // ---------------- per-batch compute block ----------------
    __shared__ float keys_sh[Hh * Ww];     // 8 KB
    __shared__ float ev_sh[NWn * Ww];      // 2 KB
    __shared__ float wv_sh[NWn * Ww];      // 2 KB
    __shared__ float sharp_sh[Hh * Mm];    // 32 KB
    __shared__ float keynorm_sh[Hh];
    __shared__ float splus_sh[Hh];
    __shared__ float rwsum_sh[NRn];
    __shared__ float fg_sh[NRn];
    __shared__ float red[8];

    int b = blockIdx.x;
    int warp = tid >> 5, lane = tid & 31;

    // stage small per-batch operands
    for (int i = tid; i < Hh * Ww; i += 256) keys_sh[i] = keys[(size_t)b * Hh * Ww + i];
    for (int i = tid; i < NWn * Ww; i += 256) {
        ev_sh[i] = ev[(size_t)b * NWn * Ww + i];
        wv_sh[i] = wv[(size_t)b * NWn * Ww + i];
    }
    // precedence passthrough: out_prec[b] = write_weights[b]
    for (int i = tid; i < NWn * Mm; i += 256)
        out_prec[(size_t)b * NWn * Mm + i] = ww[(size_t)b * NWn * Mm + i];
    if (tid < NRn) fg_sh[tid] = fg[b * NRn + tid];
    __syncthreads();

    // key norms + softplus (warp h handles head h)
    if (warp < Hh) {
        float s = 0.f;
        #pragma unroll
        for (int i = lane; i < Ww; i += 32) {
            float v = keys_sh[warp * Ww + i];
            s += v * v;
        }
        #pragma unroll
        for (int o = 16; o; o >>= 1) s += __shfl_xor_sync(0xffffffffu, s, o);
        if (lane == 0) {
            keynorm_sh[warp] = sqrtf(s + 1e-6f);
            float x = strengths[b * Hh + warp];
            splus_sh[warp] = (x > 20.f) ? x : log1pf(expf(x));
        }
    }
    // read-weight row sums (warp n < 4 handles read head n)
    if (warp < NRn) {
        const float* rp = rw + (size_t)(b * NRn + warp) * Mm;
        float s = 0.f;
        for (int i = lane; i < Mm; i += 32) s += rp[i];
        #pragma unroll
        for (int o = 16; o; o >>= 1) s += __shfl_xor_sync(0xffffffffu, s, o);
        if (lane == 0) rwsum_sh[warp] = s;
    }
    __syncthreads();

    // main loop: warp per memory row, 128 iterations cover m=0..1023
    const float4* k4  = (const float4*)keys_sh;
    const float4* e4p = (const float4*)ev_sh;
    const float4* v4p = (const float4*)wv_sh;

    for (int it = 0; it < 128; it++) {
        int m = it * 8 + warp;
        const float4* mrow = (const float4*)(memory  + (size_t)(b * Mm + m) * Ww);
        float4*       orow = (float4*)      (out_mem + (size_t)(b * Mm + m) * Ww);

        float w0 = ww[(size_t)(b * NWn + 0) * Mm + m];
        float w1 = ww[(size_t)(b * NWn + 1) * Mm + m];

        float norm2 = 0.f;
        float dot[Hh];
        #pragma unroll
        for (int h = 0; h < Hh; h++) dot[h] = 0.f;

        #pragma unroll
        for (int j = 0; j < 2; j++) {
            int i4 = lane + j * 32;
            float4 mv = mrow[i4];
            float4 e0 = e4p[i4], e1 = e4p[64 + i4];
            float4 v0 = v4p[i4], v1 = v4p[64 + i4];

            float4 o;
            float ex = fminf(fmaxf(w0 * e0.x + w1 * e1.x, 0.f), 1.f);
            float ey = fminf(fmaxf(w0 * e0.y + w1 * e1.y, 0.f), 1.f);
            float ez = fminf(fmaxf(w0 * e0.z + w1 * e1.z, 0.f), 1.f);
            float ew = fminf(fmaxf(w0 * e0.w + w1 * e1.w, 0.f), 1.f);
            o.x = mv.x * (1.f - ex) + w0 * v0.x + w1 * v1.x;
            o.y = mv.y * (1.f - ey) + w0 * v0.y + w1 * v1.y;
            o.z = mv.z * (1.f - ez) + w0 * v0.z + w1 * v1.z;
            o.w = mv.w * (1.f - ew) + w0 * v0.w + w1 * v1.w;
            orow[i4] = o;

            norm2 += mv.x * mv.x + mv.y * mv.y + mv.z * mv.z + mv.w * mv.w;

            #pragma unroll
            for (int h = 0; h < Hh; h++) {
                float4 kv = k4[h * 64 + i4];
                dot[h] += kv.x * mv.x + kv.y * mv.y + kv.z * mv.z + kv.w * mv.w;
            }
        }

        #pragma unroll
        for (int o = 16; o; o >>= 1) {
            norm2 += __shfl_xor_sync(0xffffffffu, norm2, o);
            #pragma unroll
            for (int h = 0; h < Hh; h++)
                dot[h] += __shfl_xor_sync(0xffffffffu, dot[h], o);
        }

        float mn = sqrtf(norm2 + 1e-6f);

        if (lane < Hh) {
            float myd = 0.f;
            #pragma unroll
            for (int h = 0; h < Hh; h++) if (lane == h) myd = dot[h];
            sharp_sh[lane * Mm + m] =
                myd / (mn * keynorm_sh[lane] + 1e-6f) * splus_sh[lane];
        }

        if (lane == 8) {
            float u = pu[(size_t)b * Mm + m] + w0 + w1;
            #pragma unroll
            for (int n = 0; n < NRn; n++)
                u -= rw[(size_t)(b * NRn + n) * Mm + m] * fg_sh[n];
            out_usage[(size_t)b * Mm + m] = fminf(fmaxf(u, 0.f), 1.f);
        }
    }
    __syncthreads();

    // in-block softmax over M for each head
    for (int h = 0; h < Hh; h++) {
        const float* sp = sharp_sh + h * Mm;
        float v[4];
        float mx = -INFINITY;
        #pragma unroll
        for (int j = 0; j < 4; j++) { v[j] = sp[tid + j * 256]; mx = fmaxf(mx, v[j]); }
        #pragma unroll
        for (int o = 16; o; o >>= 1) mx = fmaxf(mx, __shfl_xor_sync(0xffffffffu, mx, o));
        if (lane == 0) red[warp] = mx;
        __syncthreads();
        float bm = red[0];
        #pragma unroll
        for (int i = 1; i < 8; i++) bm = fmaxf(bm, red[i]);
        __syncthreads();

        float s = 0.f;
        #pragma unroll
        for (int j = 0; j < 4; j++) { v[j] = expf(v[j] - bm); s += v[j]; }
        #pragma unroll
        for (int o = 16; o; o >>= 1) s += __shfl_xor_sync(0xffffffffu, s, o);
        if (lane == 0) red[warp] = s;
        __syncthreads();
        float bs = 0.f;
        #pragma unroll
        for (int i = 0; i < 8; i++) bs += red[i];
        float inv = 1.f / bs;

        float* op = out_cos + (size_t)(b * Hh + h) * Mm;
        #pragma unroll
        for (int j = 0; j < 4; j++) op[tid + j * 256] = v[j] * inv;
        __syncthreads();
    }

    // read_output[b,w] = sum_n rwsum[n] * rv[b,n,w]   (256 threads = 256 w)
    {
        float s = 0.f;
        #pragma unroll
        for (int n = 0; n < NRn; n++)
            s += rwsum_sh[n] * rv[(size_t)(b * NRn + n) * Ww + tid];
        out_read[(size_t)b * Ww + tid] = s;
    }
}

// ---------------------------------------------------------------------------
extern "C" void kernel_launch(void* const* d_in, const int* in_sizes, int n_in,
                              void* d_out, int out_size) {
    const float* memory    = (const float*)d_in[0];
    const float* keys      = (const float*)d_in[1];
    const float* strengths = (const float*)d_in[2];
    const float* ww        = (const float*)d_in[3];
    const float* fg        = (const float*)d_in[4];
    const float* rw        = (const float*)d_in[5];
    const float* prev_link = (const float*)d_in[6];
    // d_in[7] = prev_precedence_weights (unused)
    const float* pu        = (const float*)d_in[8];
    const float* ev        = (const float*)d_in[9];
    const float* wv        = (const float*)d_in[10];
    const float* rv        = (const float*)d_in[11];
    float* out = (float*)d_out;

    const size_t N_MEM  = (size_t)Bb * Mm * Ww;
    const size_t N_COS  = (size_t)Bb * Hh * Mm;
    const size_t N_LINK = (size_t)Bb * NWn * Mm * Mm;
    const size_t N_PREC = (size_t)Bb * NWn * Mm;
    const size_t N_US   = (size_t)Bb * Mm;

    float* out_mem   = out;
    float* out_cos   = out + N_MEM;
    float* out_link  = out_cos + N_COS;
    float* out_prec  = out_link + N_LINK;
    float* out_usage = out_prec + N_PREC;
    float* out_read  = out_usage + N_US;

    fused_kernel<<<16 + COPY_BLOCKS, 256>>>(
        memory, keys, strengths, ww, fg, rw, prev_link, pu, ev, wv, rv,
        out_mem, out_cos, out_link, out_prec, out_usage, out_read);
}